// round 11
// baseline (speedup 1.0000x reference)
#include <cuda_runtime.h>
#include <cuda_fp16.h>
#include <cstdint>

#define B_ 4
#define N_ 4096
#define D_ 64
#define PAD 68
#define HW_ (64*64)
#define ELEMS (B_*64*64*64)
#define NC_ 19

// Scratch
__device__ float g_ot1[B_*D_*N_];     // height-attn O, transposed [b][d][s]
__device__ float g_ot2[B_*D_*N_];     // width-attn  O, transposed [b][d][s]
__device__ float g_vpart[B_*64*64];   // per-CTA column partial sums of v' = 0.5v
// fp16 operands, packed half2 words, natural layout [b][s][d]; v stores 0.5*v
__device__ __align__(128) unsigned g_q16[B_*N_*D_/2];
__device__ __align__(128) unsigned g_v16[B_*N_*D_/2];

// ---------------------------------------------------------------------------
__device__ __forceinline__ float sigmoidf_(float x) {
    return __fdividef(1.f, 1.f + __expf(-x));
}
__device__ __forceinline__ uint32_t smem_u32(const void* p) {
    uint32_t a;
    asm("{ .reg .u64 t; cvta.to.shared.u64 t, %1; cvt.u32.u64 %0, t; }" : "=r"(a) : "l"(p));
    return a;
}
__device__ __forceinline__ unsigned pack2h(float a, float b) {
    __half2 h = __floats2half2_rn(a, b);
    return *reinterpret_cast<unsigned*>(&h);
}
__device__ __forceinline__ float tanh_ap(float x) {
    float y;
    asm("tanh.approx.f32 %0, %1;" : "=f"(y) : "f"(x));
    return y;
}
__device__ __forceinline__ void ldsm4(uint32_t* r, uint32_t addr) {
    asm volatile("ldmatrix.sync.aligned.m8n8.x4.shared.b16 {%0,%1,%2,%3}, [%4];"
                 : "=r"(r[0]), "=r"(r[1]), "=r"(r[2]), "=r"(r[3]) : "r"(addr));
}
__device__ __forceinline__ void ldsm4t(uint32_t* r, uint32_t addr) {
    asm volatile("ldmatrix.sync.aligned.m8n8.x4.trans.shared.b16 {%0,%1,%2,%3}, [%4];"
                 : "=r"(r[0]), "=r"(r[1]), "=r"(r[2]), "=r"(r[3]) : "r"(addr));
}
__device__ __forceinline__ void mma16816(float* c, const uint32_t* a,
                                         uint32_t b0, uint32_t b1) {
    asm volatile("mma.sync.aligned.m16n8k16.row.col.f32.f16.f16.f32 "
                 "{%0,%1,%2,%3}, {%4,%5,%6,%7}, {%8,%9}, {%0,%1,%2,%3};"
                 : "+f"(c[0]), "+f"(c[1]), "+f"(c[2]), "+f"(c[3])
                 : "r"(a[0]), "r"(a[1]), "r"(a[2]), "r"(a[3]), "r"(b0), "r"(b1));
}
__device__ __forceinline__ void cpa16(uint32_t s, const void* g) {
    asm volatile("cp.async.cg.shared.global [%0], [%1], 16;"
                 :: "r"(s), "l"(__cvta_generic_to_global(g)) : "memory");
}
#define CP_COMMIT() asm volatile("cp.async.commit_group;" ::: "memory")

// ---------------------------------------------------------------------------
// q/v projection -> fp16 (v scaled by 0.5), plus vsum column partials.
// LAYOUT 0: x[b,s,d] = feature[b,d,w,c], s=w*64+c
// LAYOUT 1: x[b,s,d] = feature[b,h,d,c] + hg*Ot1[b][h][d*64+c]  (x1 inline)
// ---------------------------------------------------------------------------
template<int LAYOUT>
__global__ __launch_bounds__(256) void qv_kernel(
    const float* __restrict__ src,
    const float* __restrict__ wq, const float* __restrict__ bq,
    const float* __restrict__ wv, const float* __restrict__ bv,
    const float* __restrict__ gate)
{
    extern __shared__ float sm[];
    float* sXt = sm;
    float* sWq = sm + D_*PAD;
    float* sWv = sm + 2*D_*PAD;

    int b = blockIdx.y, s0 = blockIdx.x * 64, tid = threadIdx.x;
    int hw0 = s0 >> 6;

    for (int i = tid; i < 64*16; i += 256) {
        int k = i >> 4, c4 = (i & 15) * 4;
        *(float4*)&sWq[k*PAD + c4] = *(const float4*)&wq[k*64 + c4];
        *(float4*)&sWv[k*PAD + c4] = *(const float4*)&wv[k*64 + c4];
    }
    if (LAYOUT == 0) {
        for (int i = tid; i < 64*64; i += 256) {
            int d = i >> 6, r = i & 63;
            sXt[d*PAD + r] = src[((b*64 + d)*64 + hw0)*64 + r];
        }
    } else {
        float hg = gate[0];
        for (int i = tid; i < 64*64; i += 256) {
            int d = i >> 6, r = i & 63;
            float fv = src[((b*64 + hw0)*64 + d)*64 + r];
            float ov = g_ot1[(size_t)(b*64 + hw0)*4096 + d*64 + r];
            sXt[d*PAD + r] = fv + hg * ov;
        }
    }
    __syncthreads();

    int ty = tid >> 4, tx = tid & 15;
    float qa[4][4] = {{0.f}}, va[4][4] = {{0.f}};

    #pragma unroll 4
    for (int k = 0; k < 64; k++) {
        float4 xr  = *(const float4*)&sXt[k*PAD + ty*4];
        float4 wqc = *(const float4*)&sWq[k*PAD + tx*4];
        float4 wvc = *(const float4*)&sWv[k*PAD + tx*4];
        float xa[4]  = {xr.x, xr.y, xr.z, xr.w};
        float wqa[4] = {wqc.x, wqc.y, wqc.z, wqc.w};
        float wva[4] = {wvc.x, wvc.y, wvc.z, wvc.w};
        #pragma unroll
        for (int i = 0; i < 4; i++)
            #pragma unroll
            for (int j = 0; j < 4; j++) {
                qa[i][j] += xa[i] * wqa[j];
                va[i][j] += xa[i] * wva[j];
            }
    }

    float4 bq4 = *(const float4*)&bq[tx*4];
    float4 bv4 = *(const float4*)&bv[tx*4];
    float bqa[4] = {bq4.x, bq4.y, bq4.z, bq4.w};
    float bva[4] = {bv4.x, bv4.y, bv4.z, bv4.w};

    #pragma unroll
    for (int i = 0; i < 4; i++) {
        int s = s0 + ty*4 + i;
        unsigned base = (unsigned)((b*N_ + s)*32 + tx*2);
        g_q16[base]   = pack2h(qa[i][0]+bqa[0], qa[i][1]+bqa[1]);
        g_q16[base+1] = pack2h(qa[i][2]+bqa[2], qa[i][3]+bqa[3]);
        g_v16[base]   = pack2h(0.5f*(va[i][0]+bva[0]), 0.5f*(va[i][1]+bva[1]));
        g_v16[base+1] = pack2h(0.5f*(va[i][2]+bva[2]), 0.5f*(va[i][3]+bva[3]));
    }

    float vs[4];
    #pragma unroll
    for (int j = 0; j < 4; j++)
        vs[j] = 0.5f*(va[0][j] + va[1][j] + va[2][j] + va[3][j] + 4.f*bva[j]);
    __syncthreads();
    #pragma unroll
    for (int j = 0; j < 4; j++) sm[ty*64 + tx*4 + j] = vs[j];
    __syncthreads();
    if (tid < 64) {
        float acc = 0.f;
        #pragma unroll
        for (int k = 0; k < 16; k++) acc += sm[k*64 + tid];
        g_vpart[(b*64 + blockIdx.x)*64 + tid] = acc;
    }
}

// ---------------------------------------------------------------------------
// HMMA fp16 sigmoid attention, 64-row Q tiles, 2 CTAs/SM.
// o = sum tanh(qk/16) * v' + sum v'   (v' = 0.5 v)
// Output TRANSPOSED: dst[b][d][s].
// ---------------------------------------------------------------------------
#define QH_OFF 0
#define BUF0 8192
#define BUFSZ 32768                 // K 16K | V 16K
#define SVS_OFF (8192 + 2*BUFSZ)    // 73728
#define ATT_SMEM (SVS_OFF + 256)    // 73984
#define OPITCH 65

__device__ __forceinline__ void load_tile(uint32_t sbuf, int b, int mt, int tid)
{
    const char* pQ = (const char*)g_q16;
    const char* pV = (const char*)g_v16;
    #pragma unroll
    for (int j = 0; j < 8; j++) {
        const char* src = (j < 4) ? pQ : pV;
        int rem = tid + (j & 3)*256;
        int r = rem >> 3, c = (rem & 7)*16;
        cpa16(sbuf + (uint32_t)((j >> 2)*16384 + r*128 + (c ^ ((r & 7) << 4))),
              src + (size_t)(b*N_ + mt + r)*128 + c);
    }
}

template<int PASS>
__global__ __launch_bounds__(256, 2) void attn_mma()
{
    extern __shared__ char smem[];
    const uint32_t sb = smem_u32(smem);
    const int tid = threadIdx.x, lane = tid & 31, wid = tid >> 5;
    const int wm = wid >> 1, wn = wid & 1;          // 4 m x 2 n
    const int b = blockIdx.y, s0 = blockIdx.x * 64; // 64-row Q tile
    const int g = lane >> 3, rr = lane & 7;
    float* dst = (PASS == 0) ? g_ot1 : g_ot2;

    // prologue: Q tile (64 rows x 128B = 8K) + K/V tile 0
    {
        const char* pQ = (const char*)g_q16;
        #pragma unroll
        for (int j = 0; j < 2; j++) {
            int rem = tid + j*256;
            int r = rem >> 3, c = (rem & 7)*16;
            cpa16(sb + QH_OFF + (uint32_t)(r*128 + (c ^ ((r & 7) << 4))),
                  pQ + (size_t)(b*N_ + s0 + r)*128 + c);
        }
    }
    load_tile(sb + BUF0, b, 0, tid);
    CP_COMMIT();

    // reduce vsum partials while tile 0 is in flight
    if (tid < 64) {
        float a = 0.f;
        #pragma unroll
        for (int k = 0; k < 64; k++) a += g_vpart[(b*64 + k)*64 + tid];
        ((float*)(smem + SVS_OFF))[tid] = a;
    }

    uint32_t qf[4][4];            // Q fragments [kk][4] — single m16 tile per warp
    float oacc[8][4];
    #pragma unroll
    for (int j = 0; j < 8; j++)
        #pragma unroll
        for (int q = 0; q < 4; q++) oacc[j][q] = 0.f;

    for (int t = 0; t < 32; t++) {
        if (t < 31) {
            load_tile(sb + BUF0 + (uint32_t)(((t+1) & 1)*BUFSZ), b, (t+1) << 7, tid);
            CP_COMMIT();
            asm volatile("cp.async.wait_group 1;" ::: "memory");
        } else {
            asm volatile("cp.async.wait_group 0;" ::: "memory");
        }
        __syncthreads();

        const uint32_t kb = sb + BUF0 + (uint32_t)((t & 1)*BUFSZ);

        if (t == 0) {
            #pragma unroll
            for (int kk = 0; kk < 4; kk++) {
                int row = wm*16 + rr + ((g & 1) << 3);
                uint32_t cb = (uint32_t)(kk*32 + ((g >> 1) << 4));
                ldsm4(qf[kk], sb + QH_OFF + (uint32_t)(row*128) + (cb ^ ((row & 7) << 4)));
            }
        }

        // per 16-key group: QK, tanh, SV
        #pragma unroll
        for (int p = 0; p < 4; p++) {
            float sacc[2][4];
            #pragma unroll
            for (int jj = 0; jj < 2; jj++)
                #pragma unroll
                for (int q = 0; q < 4; q++) sacc[jj][q] = 0.f;

            #pragma unroll
            for (int kk = 0; kk < 4; kk++) {
                int key = wn*64 + p*16 + rr + ((g >> 1) << 3);
                uint32_t cb = (uint32_t)(kk*32 + ((g & 1) << 4));
                uint32_t ad = kb + (uint32_t)(key*128) + (cb ^ ((key & 7) << 4));
                uint32_t bk[4];
                ldsm4(bk, ad);
                mma16816(sacc[0], qf[kk], bk[0], bk[1]);
                mma16816(sacc[1], qf[kk], bk[2], bk[3]);
            }

            uint32_t as_[4];
            #pragma unroll
            for (int jj = 0; jj < 2; jj++)
                #pragma unroll
                for (int q = 0; q < 4; q++)
                    sacc[jj][q] = tanh_ap(sacc[jj][q] * 0.0625f);
            as_[0] = pack2h(sacc[0][0], sacc[0][1]);
            as_[1] = pack2h(sacc[0][2], sacc[0][3]);
            as_[2] = pack2h(sacc[1][0], sacc[1][1]);
            as_[3] = pack2h(sacc[1][2], sacc[1][3]);

            #pragma unroll
            for (int dp = 0; dp < 4; dp++) {
                int key = wn*64 + p*16 + rr + ((g & 1) << 3);
                uint32_t cb = (uint32_t)(dp*32 + ((g >> 1) << 4));
                uint32_t ad = kb + 16384u + (uint32_t)(key*128) + (cb ^ ((key & 7) << 4));
                uint32_t vv[4];
                ldsm4t(vv, ad);
                mma16816(oacc[2*dp],   as_, vv[0], vv[1]);
                mma16816(oacc[2*dp+1], as_, vv[2], vv[3]);
            }
        }
        __syncthreads();
    }

    // ---- reduce across wn, add vsum, write TRANSPOSED dst[b][col][s0+row] ----
    float* ored = (float*)(smem + BUF0);      // [64][OPITCH]
    if (wn == 1) {
        #pragma unroll
        for (int dj = 0; dj < 8; dj++) {
            int row = wm*16 + (lane >> 2);
            int col = dj*8 + (lane & 3)*2;
            ored[row*OPITCH + col]       = oacc[dj][0];
            ored[row*OPITCH + col + 1]   = oacc[dj][1];
            ored[(row+8)*OPITCH + col]   = oacc[dj][2];
            ored[(row+8)*OPITCH + col+1] = oacc[dj][3];
        }
    }
    __syncthreads();
    if (wn == 0) {
        #pragma unroll
        for (int dj = 0; dj < 8; dj++) {
            int row = wm*16 + (lane >> 2);
            int col = dj*8 + (lane & 3)*2;
            ored[row*OPITCH + col]       += oacc[dj][0];
            ored[row*OPITCH + col + 1]   += oacc[dj][1];
            ored[(row+8)*OPITCH + col]   += oacc[dj][2];
            ored[(row+8)*OPITCH + col+1] += oacc[dj][3];
        }
    }
    __syncthreads();
    const float* svs = (const float*)(smem + SVS_OFF);
    for (int i = tid; i < 4096; i += 256) {
        int col = i >> 6, row = i & 63;
        dst[(size_t)(b*64 + col)*4096 + s0 + row] = ored[row*OPITCH + col] + svs[col];
    }
}

// ---------------------------------------------------------------------------
// out = p * (2*feature + hg*oh + wg*ow), p fused per-pixel.
// ---------------------------------------------------------------------------
__global__ __launch_bounds__(256) void final_kernel(
    const float* __restrict__ feature, const float* __restrict__ predict,
    const float* __restrict__ cw, const float* __restrict__ cb,
    const float* __restrict__ hgate, const float* __restrict__ wgate,
    float* __restrict__ out)
{
    __shared__ float sp[4];
    int tid = threadIdx.x;
    int idx = blockIdx.x * 256 + tid;
    if (tid < 4) {
        int pix = blockIdx.x * 4 + tid;
        float acc = cb[0];
        #pragma unroll
        for (int k = 0; k < NC_; k++)
            acc += (1.f - sigmoidf_(predict[pix*NC_ + k])) * cw[k];
        sp[tid] = acc;
    }
    __syncthreads();
    float hg = hgate[0], wg = wgate[0];
    int c = idx & 63, w = (idx >> 6) & 63, h = (idx >> 12) & 63, b = idx >> 18;
    float oh = g_ot1[(size_t)(b*64 + h)*4096 + w*64 + c];
    float ow = g_ot2[(size_t)(b*64 + w)*4096 + h*64 + c];
    out[idx] = sp[tid >> 6] * (2.f*feature[idx] + hg*oh + wg*ow);
}

extern "C" void kernel_launch(void* const* d_in, const int* in_sizes, int n_in,
                              void* d_out, int out_size)
{
    const float* feature = (const float*)d_in[0];
    const float* predict = (const float*)d_in[1];
    const float* hq_w = (const float*)d_in[2];
    const float* hq_b = (const float*)d_in[3];
    const float* hv_w = (const float*)d_in[4];
    const float* hv_b = (const float*)d_in[5];
    const float* wq_w = (const float*)d_in[6];
    const float* wq_b = (const float*)d_in[7];
    const float* wv_w = (const float*)d_in[8];
    const float* wv_b = (const float*)d_in[9];
    const float* h_gate = (const float*)d_in[10];
    const float* w_gate = (const float*)d_in[11];
    const float* conv_w = (const float*)d_in[12];
    const float* conv_b = (const float*)d_in[13];
    float* out = (float*)d_out;

    const int qv_smem = 3 * D_ * PAD * (int)sizeof(float);
    cudaFuncSetAttribute(qv_kernel<0>, cudaFuncAttributeMaxDynamicSharedMemorySize, qv_smem);
    cudaFuncSetAttribute(qv_kernel<1>, cudaFuncAttributeMaxDynamicSharedMemorySize, qv_smem);
    cudaFuncSetAttribute(attn_mma<0>, cudaFuncAttributeMaxDynamicSharedMemorySize, ATT_SMEM);
    cudaFuncSetAttribute(attn_mma<1>, cudaFuncAttributeMaxDynamicSharedMemorySize, ATT_SMEM);

    dim3 gqv(N_/64, B_);
    dim3 gat(N_/64, B_);      // 64-row Q tiles -> 256 CTAs

    // Pass 1: height attention
    qv_kernel<0><<<gqv, 256, qv_smem>>>(feature, hq_w, hq_b, hv_w, hv_b, nullptr);
    attn_mma<0><<<gat, 256, ATT_SMEM>>>();

    // Pass 2: width attention (x1 composed inline)
    qv_kernel<1><<<gqv, 256, qv_smem>>>(feature, wq_w, wq_b, wv_w, wv_b, h_gate);
    attn_mma<1><<<gat, 256, ATT_SMEM>>>();

    // Fused gate + output
    final_kernel<<<ELEMS/256, 256>>>(feature, predict, conv_w, conv_b,
                                     h_gate, w_gate, out);
}

// round 13
// speedup vs baseline: 1.1003x; 1.1003x over previous
#include <cuda_runtime.h>
#include <cuda_fp16.h>
#include <cstdint>

#define B_ 4
#define N_ 4096
#define D_ 64
#define PAD 68
#define HW_ (64*64)
#define ELEMS (B_*64*64*64)
#define NC_ 19

// Scratch
__device__ float g_ot1[B_*D_*N_];     // height-attn O, transposed [b][d][s]
__device__ float g_ot2[B_*D_*N_];     // width-attn  O, transposed [b][d][s]
__device__ float g_vpart[B_*64*64];   // per-CTA column partial sums of v' = 0.5v
// fp16 operands, packed half2, [b][s][d]; q stores q/4 (so q'q'^T = qq^T/16), v stores v/2
__device__ __align__(128) unsigned g_q16[B_*N_*D_/2];
__device__ __align__(128) unsigned g_v16[B_*N_*D_/2];

// ---------------------------------------------------------------------------
__device__ __forceinline__ float sigmoidf_(float x) {
    return __fdividef(1.f, 1.f + __expf(-x));
}
__device__ __forceinline__ uint32_t smem_u32(const void* p) {
    uint32_t a;
    asm("{ .reg .u64 t; cvta.to.shared.u64 t, %1; cvt.u32.u64 %0, t; }" : "=r"(a) : "l"(p));
    return a;
}
__device__ __forceinline__ unsigned pack2h(float a, float b) {
    __half2 h = __floats2half2_rn(a, b);
    return *reinterpret_cast<unsigned*>(&h);
}
__device__ __forceinline__ uint32_t tanh16x2(uint32_t x) {
    uint32_t y;
    asm("tanh.approx.f16x2 %0, %1;" : "=r"(y) : "r"(x));
    return y;
}
__device__ __forceinline__ void ldsm4(uint32_t* r, uint32_t addr) {
    asm volatile("ldmatrix.sync.aligned.m8n8.x4.shared.b16 {%0,%1,%2,%3}, [%4];"
                 : "=r"(r[0]), "=r"(r[1]), "=r"(r[2]), "=r"(r[3]) : "r"(addr));
}
__device__ __forceinline__ void ldsm4t(uint32_t* r, uint32_t addr) {
    asm volatile("ldmatrix.sync.aligned.m8n8.x4.trans.shared.b16 {%0,%1,%2,%3}, [%4];"
                 : "=r"(r[0]), "=r"(r[1]), "=r"(r[2]), "=r"(r[3]) : "r"(addr));
}
// non-volatile: pure register op, lets ptxas interleave across groups
__device__ __forceinline__ void mma16816(float* c, const uint32_t* a,
                                         uint32_t b0, uint32_t b1) {
    asm("mma.sync.aligned.m16n8k16.row.col.f32.f16.f16.f32 "
        "{%0,%1,%2,%3}, {%4,%5,%6,%7}, {%8,%9}, {%0,%1,%2,%3};"
        : "+f"(c[0]), "+f"(c[1]), "+f"(c[2]), "+f"(c[3])
        : "r"(a[0]), "r"(a[1]), "r"(a[2]), "r"(a[3]), "r"(b0), "r"(b1));
}
__device__ __forceinline__ void cpa16(uint32_t s, const void* g) {
    asm volatile("cp.async.cg.shared.global [%0], [%1], 16;"
                 :: "r"(s), "l"(__cvta_generic_to_global(g)) : "memory");
}
#define CP_COMMIT() asm volatile("cp.async.commit_group;" ::: "memory")

// ---------------------------------------------------------------------------
// q/v projection -> fp16 (q scaled 1/4, v scaled 1/2), vsum column partials.
// LAYOUT 0: x[b,s,d] = feature[b,d,w,c], s=w*64+c
// LAYOUT 1: x[b,s,d] = feature[b,h,d,c] + hg*Ot1[b][h][d*64+c]
// ---------------------------------------------------------------------------
template<int LAYOUT>
__global__ __launch_bounds__(256) void qv_kernel(
    const float* __restrict__ src,
    const float* __restrict__ wq, const float* __restrict__ bq,
    const float* __restrict__ wv, const float* __restrict__ bv,
    const float* __restrict__ gate)
{
    extern __shared__ float sm[];
    float* sXt = sm;
    float* sWq = sm + D_*PAD;
    float* sWv = sm + 2*D_*PAD;

    int b = blockIdx.y, s0 = blockIdx.x * 64, tid = threadIdx.x;
    int hw0 = s0 >> 6;

    for (int i = tid; i < 64*16; i += 256) {
        int k = i >> 4, c4 = (i & 15) * 4;
        *(float4*)&sWq[k*PAD + c4] = *(const float4*)&wq[k*64 + c4];
        *(float4*)&sWv[k*PAD + c4] = *(const float4*)&wv[k*64 + c4];
    }
    if (LAYOUT == 0) {
        for (int i = tid; i < 64*64; i += 256) {
            int d = i >> 6, r = i & 63;
            sXt[d*PAD + r] = src[((b*64 + d)*64 + hw0)*64 + r];
        }
    } else {
        float hg = gate[0];
        for (int i = tid; i < 64*64; i += 256) {
            int d = i >> 6, r = i & 63;
            float fv = src[((b*64 + hw0)*64 + d)*64 + r];
            float ov = g_ot1[(size_t)(b*64 + hw0)*4096 + d*64 + r];
            sXt[d*PAD + r] = fv + hg * ov;
        }
    }
    __syncthreads();

    int ty = tid >> 4, tx = tid & 15;
    float qa[4][4] = {{0.f}}, va[4][4] = {{0.f}};

    #pragma unroll 4
    for (int k = 0; k < 64; k++) {
        float4 xr  = *(const float4*)&sXt[k*PAD + ty*4];
        float4 wqc = *(const float4*)&sWq[k*PAD + tx*4];
        float4 wvc = *(const float4*)&sWv[k*PAD + tx*4];
        float xa[4]  = {xr.x, xr.y, xr.z, xr.w};
        float wqa[4] = {wqc.x, wqc.y, wqc.z, wqc.w};
        float wva[4] = {wvc.x, wvc.y, wvc.z, wvc.w};
        #pragma unroll
        for (int i = 0; i < 4; i++)
            #pragma unroll
            for (int j = 0; j < 4; j++) {
                qa[i][j] += xa[i] * wqa[j];
                va[i][j] += xa[i] * wva[j];
            }
    }

    float4 bq4 = *(const float4*)&bq[tx*4];
    float4 bv4 = *(const float4*)&bv[tx*4];
    float bqa[4] = {bq4.x, bq4.y, bq4.z, bq4.w};
    float bva[4] = {bv4.x, bv4.y, bv4.z, bv4.w};

    #pragma unroll
    for (int i = 0; i < 4; i++) {
        int s = s0 + ty*4 + i;
        unsigned base = (unsigned)((b*N_ + s)*32 + tx*2);
        // q' = q/4: since K == Q, (q/4)(q/4)^T = qq^T/16 = tanh argument directly
        g_q16[base]   = pack2h(0.25f*(qa[i][0]+bqa[0]), 0.25f*(qa[i][1]+bqa[1]));
        g_q16[base+1] = pack2h(0.25f*(qa[i][2]+bqa[2]), 0.25f*(qa[i][3]+bqa[3]));
        // v' = v/2
        g_v16[base]   = pack2h(0.5f*(va[i][0]+bva[0]), 0.5f*(va[i][1]+bva[1]));
        g_v16[base+1] = pack2h(0.5f*(va[i][2]+bva[2]), 0.5f*(va[i][3]+bva[3]));
    }

    float vs[4];
    #pragma unroll
    for (int j = 0; j < 4; j++)
        vs[j] = 0.5f*(va[0][j] + va[1][j] + va[2][j] + va[3][j] + 4.f*bva[j]);
    __syncthreads();
    #pragma unroll
    for (int j = 0; j < 4; j++) sm[ty*64 + tx*4 + j] = vs[j];
    __syncthreads();
    if (tid < 64) {
        float acc = 0.f;
        #pragma unroll
        for (int k = 0; k < 16; k++) acc += sm[k*64 + tid];
        g_vpart[(b*64 + blockIdx.x)*64 + tid] = acc;
    }
}

// ---------------------------------------------------------------------------
// HMMA fp16 sigmoid attention, 128-row Q tiles, 4-stage cp.async ring,
// one barrier per tile.  o = sum tanh(q'q'^T)*v' + sum v'
// Output TRANSPOSED: dst[b][d][s].
// ---------------------------------------------------------------------------
#define QH_OFF 0
#define BUF0 16384
#define BUFSZ 32768                   // K 16K | V 16K per stage
#define SVS_OFF (16384 + 4*32768)     // 147456
#define ATT_SMEM (SVS_OFF + 256)      // 147712
#define OPITCH 65

__device__ __forceinline__ void load_tile(uint32_t sbuf, int b, int mt, int tid)
{
    const char* pQ = (const char*)g_q16;
    const char* pV = (const char*)g_v16;
    #pragma unroll
    for (int j = 0; j < 8; j++) {
        const char* src = (j < 4) ? pQ : pV;
        int rem = tid + (j & 3)*256;
        int r = rem >> 3, c = (rem & 7)*16;
        cpa16(sbuf + (uint32_t)((j >> 2)*16384 + r*128 + (c ^ ((r & 7) << 4))),
              src + (size_t)(b*N_ + mt + r)*128 + c);
    }
}

template<int PASS>
__global__ __launch_bounds__(256, 1) void attn_mma()
{
    extern __shared__ char smem[];
    const uint32_t sb = smem_u32(smem);
    const int tid = threadIdx.x, lane = tid & 31, wid = tid >> 5;
    const int wm = wid >> 1, wn = wid & 1;
    const int b = blockIdx.y, s0 = blockIdx.x * 128;
    const int g = lane >> 3, rr = lane & 7;
    float* dst = (PASS == 0) ? g_ot1 : g_ot2;

    // prologue: Q tile + tile0 (group 0), tile1 (group 1)
    {
        const char* pQ = (const char*)g_q16;
        #pragma unroll
        for (int j = 0; j < 4; j++) {
            int rem = tid + j*256;
            int r = rem >> 3, c = (rem & 7)*16;
            cpa16(sb + QH_OFF + (uint32_t)(r*128 + (c ^ ((r & 7) << 4))),
                  pQ + (size_t)(b*N_ + s0 + r)*128 + c);
        }
    }
    load_tile(sb + BUF0, b, 0, tid);
    CP_COMMIT();
    load_tile(sb + BUF0 + BUFSZ, b, 128, tid);
    CP_COMMIT();

    // reduce vsum partials while tiles are in flight
    if (tid < 64) {
        float a = 0.f;
        #pragma unroll
        for (int k = 0; k < 64; k++) a += g_vpart[(b*64 + k)*64 + tid];
        ((float*)(smem + SVS_OFF))[tid] = a;
    }

    uint32_t qf[2][4][4];
    float oacc[2][8][4];
    #pragma unroll
    for (int mi = 0; mi < 2; mi++)
        #pragma unroll
        for (int j = 0; j < 8; j++)
            #pragma unroll
            for (int q = 0; q < 4; q++) oacc[mi][j][q] = 0.f;

    for (int t = 0; t < 32; t++) {
        if (t < 30)
            load_tile(sb + BUF0 + (uint32_t)(((t+2) & 3)*BUFSZ), b, (t+2) << 7, tid);
        CP_COMMIT();   // empty groups at t>=30 keep wait count uniform
        asm volatile("cp.async.wait_group 2;" ::: "memory");
        __syncthreads();   // data visibility for buf[t&3]

        const uint32_t kb = sb + BUF0 + (uint32_t)((t & 3)*BUFSZ);

        if (t == 0) {
            #pragma unroll
            for (int kk = 0; kk < 4; kk++)
                #pragma unroll
                for (int mi = 0; mi < 2; mi++) {
                    int row = wm*32 + mi*16 + rr + ((g & 1) << 3);
                    uint32_t cb = (uint32_t)(kk*32 + ((g >> 1) << 4));
                    ldsm4(qf[mi][kk], sb + QH_OFF + (uint32_t)(row*128) + (cb ^ ((row & 7) << 4)));
                }
        }

        #pragma unroll
        for (int p = 0; p < 4; p++) {
            float sacc[2][2][4];
            #pragma unroll
            for (int mi = 0; mi < 2; mi++)
                #pragma unroll
                for (int jj = 0; jj < 2; jj++)
                    #pragma unroll
                    for (int q = 0; q < 4; q++) sacc[mi][jj][q] = 0.f;

            #pragma unroll
            for (int kk = 0; kk < 4; kk++) {
                int key = wn*64 + p*16 + rr + ((g >> 1) << 3);
                uint32_t cb = (uint32_t)(kk*32 + ((g & 1) << 4));
                uint32_t ad = kb + (uint32_t)(key*128) + (cb ^ ((key & 7) << 4));
                uint32_t bk[4];
                ldsm4(bk, ad);
                #pragma unroll
                for (int mi = 0; mi < 2; mi++) {
                    mma16816(sacc[mi][0], qf[mi][kk], bk[0], bk[1]);
                    mma16816(sacc[mi][1], qf[mi][kk], bk[2], bk[3]);
                }
            }

            // sacc is already the tanh argument (q prescaled 1/4 on both sides)
            uint32_t as_[2][4];
            #pragma unroll
            for (int mi = 0; mi < 2; mi++) {
                as_[mi][0] = tanh16x2(pack2h(sacc[mi][0][0], sacc[mi][0][1]));
                as_[mi][1] = tanh16x2(pack2h(sacc[mi][0][2], sacc[mi][0][3]));
                as_[mi][2] = tanh16x2(pack2h(sacc[mi][1][0], sacc[mi][1][1]));
                as_[mi][3] = tanh16x2(pack2h(sacc[mi][1][2], sacc[mi][1][3]));
            }

            #pragma unroll
            for (int dp = 0; dp < 4; dp++) {
                int key = wn*64 + p*16 + rr + ((g & 1) << 3);
                uint32_t cb = (uint32_t)(dp*32 + ((g >> 1) << 4));
                uint32_t ad = kb + 16384u + (uint32_t)(key*128) + (cb ^ ((key & 7) << 4));
                uint32_t vv[4];
                ldsm4t(vv, ad);
                #pragma unroll
                for (int mi = 0; mi < 2; mi++) {
                    mma16816(oacc[mi][2*dp],   as_[mi], vv[0], vv[1]);
                    mma16816(oacc[mi][2*dp+1], as_[mi], vv[2], vv[3]);
                }
            }
        }
    }

    // ---- reduce across wn, add vsum, write TRANSPOSED dst[b][col][s0+row] ----
    float* ored = (float*)(smem + BUF0);      // [128][OPITCH]
    if (wn == 1) {
        #pragma unroll
        for (int mi = 0; mi < 2; mi++)
            #pragma unroll
            for (int dj = 0; dj < 8; dj++) {
                int row = wm*32 + mi*16 + (lane >> 2);
                int col = dj*8 + (lane & 3)*2;
                ored[row*OPITCH + col]       = oacc[mi][dj][0];
                ored[row*OPITCH + col + 1]   = oacc[mi][dj][1];
                ored[(row+8)*OPITCH + col]   = oacc[mi][dj][2];
                ored[(row+8)*OPITCH + col+1] = oacc[mi][dj][3];
            }
    }
    __syncthreads();
    if (wn == 0) {
        #pragma unroll
        for (int mi = 0; mi < 2; mi++)
            #pragma unroll
            for (int dj = 0; dj < 8; dj++) {
                int row = wm*32 + mi*16 + (lane >> 2);
                int col = dj*8 + (lane & 3)*2;
                ored[row*OPITCH + col]       += oacc[mi][dj][0];
                ored[row*OPITCH + col + 1]   += oacc[mi][dj][1];
                ored[(row+8)*OPITCH + col]   += oacc[mi][dj][2];
                ored[(row+8)*OPITCH + col+1] += oacc[mi][dj][3];
            }
    }
    __syncthreads();
    const float* svs = (const float*)(smem + SVS_OFF);
    for (int i = tid; i < 8192; i += 256) {
        int col = i >> 7, row = i & 127;
        dst[(size_t)(b*64 + col)*4096 + s0 + row] = ored[row*OPITCH + col] + svs[col];
    }
}

// ---------------------------------------------------------------------------
// out = p * (2*feature + hg*oh + wg*ow), p fused per-pixel.
// ---------------------------------------------------------------------------
__global__ __launch_bounds__(256) void final_kernel(
    const float* __restrict__ feature, const float* __restrict__ predict,
    const float* __restrict__ cw, const float* __restrict__ cb,
    const float* __restrict__ hgate, const float* __restrict__ wgate,
    float* __restrict__ out)
{
    __shared__ float sp[4];
    int tid = threadIdx.x;
    int idx = blockIdx.x * 256 + tid;
    if (tid < 4) {
        int pix = blockIdx.x * 4 + tid;
        float acc = cb[0];
        #pragma unroll
        for (int k = 0; k < NC_; k++)
            acc += (1.f - sigmoidf_(predict[pix*NC_ + k])) * cw[k];
        sp[tid] = acc;
    }
    __syncthreads();
    float hg = hgate[0], wg = wgate[0];
    int c = idx & 63, w = (idx >> 6) & 63, h = (idx >> 12) & 63, b = idx >> 18;
    float oh = g_ot1[(size_t)(b*64 + h)*4096 + w*64 + c];
    float ow = g_ot2[(size_t)(b*64 + w)*4096 + h*64 + c];
    out[idx] = sp[tid >> 6] * (2.f*feature[idx] + hg*oh + wg*ow);
}

extern "C" void kernel_launch(void* const* d_in, const int* in_sizes, int n_in,
                              void* d_out, int out_size)
{
    const float* feature = (const float*)d_in[0];
    const float* predict = (const float*)d_in[1];
    const float* hq_w = (const float*)d_in[2];
    const float* hq_b = (const float*)d_in[3];
    const float* hv_w = (const float*)d_in[4];
    const float* hv_b = (const float*)d_in[5];
    const float* wq_w = (const float*)d_in[6];
    const float* wq_b = (const float*)d_in[7];
    const float* wv_w = (const float*)d_in[8];
    const float* wv_b = (const float*)d_in[9];
    const float* h_gate = (const float*)d_in[10];
    const float* w_gate = (const float*)d_in[11];
    const float* conv_w = (const float*)d_in[12];
    const float* conv_b = (const float*)d_in[13];
    float* out = (float*)d_out;

    const int qv_smem = 3 * D_ * PAD * (int)sizeof(float);
    cudaFuncSetAttribute(qv_kernel<0>, cudaFuncAttributeMaxDynamicSharedMemorySize, qv_smem);
    cudaFuncSetAttribute(qv_kernel<1>, cudaFuncAttributeMaxDynamicSharedMemorySize, qv_smem);
    cudaFuncSetAttribute(attn_mma<0>, cudaFuncAttributeMaxDynamicSharedMemorySize, ATT_SMEM);
    cudaFuncSetAttribute(attn_mma<1>, cudaFuncAttributeMaxDynamicSharedMemorySize, ATT_SMEM);

    dim3 gqv(N_/64, B_);
    dim3 gat(N_/128, B_);

    // Pass 1: height attention
    qv_kernel<0><<<gqv, 256, qv_smem>>>(feature, hq_w, hq_b, hv_w, hv_b, nullptr);
    attn_mma<0><<<gat, 256, ATT_SMEM>>>();

    // Pass 2: width attention (x1 composed inline)
    qv_kernel<1><<<gqv, 256, qv_smem>>>(feature, wq_w, wq_b, wv_w, wv_b, h_gate);
    attn_mma<1><<<gat, 256, ATT_SMEM>>>();

    // Fused gate + output
    final_kernel<<<ELEMS/256, 256>>>(feature, predict, conv_w, conv_b,
                                     h_gate, w_gate, out);
}